// round 1
// baseline (speedup 1.0000x reference)
#include <cuda_runtime.h>

#define BB 16
#define SS 4096
#define HH 16
#define EE 64
#define SDIM 64
#define NW 127

// Scratch (device globals — no allocation allowed in kernel_launch)
__device__ float g_vs[BB*HH*SDIM*EE];   // [b][h][j][e]  column sums (sum over i)
__device__ float g_us[BB*HH*SDIM*EE];   // [b][h][i][e]  row sums    (sum over j)
__device__ float g_rv[BB*SDIM*HH*EE];   // [b][k][h][e]  RxV
__device__ float g_ru[BB*SDIM*HH*EE];   // [b][k][h][e]  RxU

// ---------------------------------------------------------------------------
// Kernel 1: row/column sums of v viewed as (b, i, j, h, e) with s = i*64+j.
// One block per (b,h). Thread: e = t&63, group g = t>>6 covers i = g,g+4,...
// Per-thread vacc[64] accumulates column sums (over its i subset); the scalar
// c is the row sum (written directly, coalesced). Cross-group reduction of
// vacc goes through shared memory atomics (16K smem atomics/block, cheap).
// ---------------------------------------------------------------------------
__global__ __launch_bounds__(256) void k_reduce(const float* __restrict__ v) {
    int bh = blockIdx.x;
    int b = bh >> 4, h = bh & 15;
    int t = threadIdx.x;
    int e = t & 63, g = t >> 6;

    __shared__ float sv[SDIM*EE];
    for (int idx = t; idx < SDIM*EE; idx += 256) sv[idx] = 0.f;
    __syncthreads();

    float vacc[SDIM];
    #pragma unroll
    for (int j = 0; j < SDIM; ++j) vacc[j] = 0.f;

    // v[b][s][h][e] ; s stride = H*E = 1024 floats
    const float* vb = v + ((size_t)b*SS*HH + h)*EE + e;

    for (int i = g; i < SDIM; i += 4) {
        const float* vrow = vb + (size_t)(i*SDIM)*HH*EE;
        float c = 0.f;
        #pragma unroll
        for (int j = 0; j < SDIM; ++j) {
            float val = vrow[(size_t)j*HH*EE];
            c += val;
            vacc[j] += val;
        }
        g_us[((size_t)bh*SDIM + i)*EE + e] = c;   // coalesced over e
    }

    #pragma unroll
    for (int j = 0; j < SDIM; ++j) atomicAdd(&sv[j*EE + e], vacc[j]);
    __syncthreads();

    for (int idx = t; idx < SDIM*EE; idx += 256)
        g_vs[(size_t)bh*SDIM*EE + idx] = sv[idx];
}

// ---------------------------------------------------------------------------
// Kernel 2: 64-tap circular convolutions (the rfft/irfft pair, done directly).
// RxV[k] = sum_j v_s[j] * w[h, (k - j + 64) mod 127]   (same for RxU).
// One block per (b,h); tiles v_s/u_s/w in smem; writes [b][k][h][e] so the
// output kernel streams contiguous 4KB rows.
// ---------------------------------------------------------------------------
__global__ __launch_bounds__(256) void k_conv(const float* __restrict__ w) {
    int bh = blockIdx.x;
    int b = bh >> 4, h = bh & 15;
    int t = threadIdx.x;

    __shared__ float vs_s[SDIM*EE];
    __shared__ float us_s[SDIM*EE];
    __shared__ float w_s[NW];

    for (int idx = t; idx < SDIM*EE; idx += 256) {
        vs_s[idx] = g_vs[(size_t)bh*SDIM*EE + idx];
        us_s[idx] = g_us[(size_t)bh*SDIM*EE + idx];
    }
    if (t < NW) w_s[t] = w[h*NW + t];
    __syncthreads();

    int e = t & 63, g = t >> 6;
    for (int k = g; k < SDIM; k += 4) {
        float rv = 0.f, ru = 0.f;
        #pragma unroll
        for (int j = 0; j < SDIM; ++j) {
            int idx = k + 64 - j;            // range [1,127]
            if (idx > 126) idx -= 127;       // 127 -> 0
            float wk = w_s[idx];
            rv += vs_s[j*EE + e] * wk;
            ru += us_s[j*EE + e] * wk;
        }
        size_t o = ((size_t)(b*SDIM + k)*HH + h)*EE + e;
        g_rv[o] = rv;
        g_ru[o] = ru;
    }
}

// ---------------------------------------------------------------------------
// Kernel 3: pbv[b, i*64+j, h, e] = RxV[...,j] + RxU[...,i].
// One block per (b,i); RxU row held in registers, RxV rows hit L2 (256KB/b).
// float4 everywhere; writes 256MB fully coalesced.
// ---------------------------------------------------------------------------
__global__ __launch_bounds__(256) void k_out(float* __restrict__ out) {
    int bi = blockIdx.x;            // b*64 + i
    int b = bi >> 6, i = bi & 63;
    int t = threadIdx.x;

    const float4* rowu = reinterpret_cast<const float4*>(g_ru + (size_t)bi*HH*EE);
    float4 uu = rowu[t];

    for (int j = 0; j < SDIM; ++j) {
        const float4* rowv = reinterpret_cast<const float4*>(g_rv + (size_t)(b*SDIM + j)*HH*EE);
        float4 vv = rowv[t];
        float4 o;
        o.x = vv.x + uu.x; o.y = vv.y + uu.y;
        o.z = vv.z + uu.z; o.w = vv.w + uu.w;
        reinterpret_cast<float4*>(out + ((size_t)b*SS + (size_t)i*SDIM + j)*HH*EE)[t] = o;
    }
}

// ---------------------------------------------------------------------------
// Kernel 4: z_pb output (65536 floats). zc[h][k] = 64 * conv(o_, w[h])[k],
// out2[(i*64+j)*16 + h] = zc[h][j] + zc[h][i]. One block per i.
// ---------------------------------------------------------------------------
__global__ __launch_bounds__(1024) void k_z(const float* __restrict__ w,
                                            const float* __restrict__ o_,
                                            float* __restrict__ out2) {
    int i = blockIdx.x;     // 0..63
    int t = threadIdx.x;    // 0..1023

    __shared__ float w_s[HH*NW];
    __shared__ float o_s[SDIM];
    __shared__ float zc_s[HH*SDIM];

    for (int idx = t; idx < HH*NW; idx += 1024) w_s[idx] = w[idx];
    if (t < SDIM) o_s[t] = o_[t];
    __syncthreads();

    {
        int h = t >> 6, k = t & 63;
        float acc = 0.f;
        #pragma unroll
        for (int j = 0; j < SDIM; ++j) {
            int idx = k + 64 - j;
            if (idx > 126) idx -= 127;
            acc += o_s[j] * w_s[h*NW + idx];
        }
        zc_s[h*SDIM + k] = acc * 64.f;
    }
    __syncthreads();

    int j = t >> 4, h = t & 15;
    out2[(size_t)i*1024 + t] = zc_s[h*SDIM + j] + zc_s[h*SDIM + i];
}

extern "C" void kernel_launch(void* const* d_in, const int* in_sizes, int n_in,
                              void* d_out, int out_size) {
    const float* v  = (const float*)d_in[0];
    const float* w  = (const float*)d_in[1];
    const float* o_ = (const float*)d_in[2];
    float* out = (float*)d_out;

    k_reduce<<<BB*HH, 256>>>(v);
    k_conv  <<<BB*HH, 256>>>(w);
    k_out   <<<BB*SDIM, 256>>>(out);
    k_z     <<<SDIM, 1024>>>(w, o_, out + (size_t)BB*SS*HH*EE);
}

// round 2
// speedup vs baseline: 1.6612x; 1.6612x over previous
#include <cuda_runtime.h>

#define BB 16
#define SS 4096
#define HH 16
#define EE 64
#define SDIM 64
#define NW 127

// Scratch (device globals — no allocation allowed in kernel_launch)
__device__ float g_vs4[4*BB*HH*SDIM*EE]; // [q][b][h][j][e] partial column sums
__device__ float g_us[BB*HH*SDIM*EE];    // [b][h][i][e]    row sums (complete)
__device__ float g_rv[BB*SDIM*HH*EE];    // [b][k][h][e]    RxV
__device__ float g_ru[BB*SDIM*HH*EE];    // [b][k][h][e]    RxU

// ---------------------------------------------------------------------------
// Kernel 1: row/column sums of v viewed as (b, i, j, h, e), s = i*64+j.
// Grid = 1024: 4 blocks per (b,h), each covering 16 i-rows (q = quarter).
// Thread (e = t&63, g = t>>6) handles i = q*16 + g*4 + m, m=0..3.
// j is tiled in chunks of 16 so per-thread live state is vloc[16]+crow[4]
// (~40 regs -> full occupancy, 16-deep load batches). v is read once ->
// __ldcs streaming loads. Column partials go to smem (conflict-free spread
// atomics), then to one of 4 global slices merged later by k_conv.
// ---------------------------------------------------------------------------
__global__ __launch_bounds__(256) void k_reduce(const float* __restrict__ v) {
    int bid = blockIdx.x;
    int bh = bid >> 2, q = bid & 3;
    int b = bh >> 4, h = bh & 15;
    int t = threadIdx.x;
    int e = t & 63, g = t >> 6;

    __shared__ float sv[SDIM*EE];
    for (int idx = t; idx < SDIM*EE; idx += 256) sv[idx] = 0.f;
    __syncthreads();

    // v offset: b*4096*1024 + (i*64+j)*1024 + h*64 + e
    const float* vb = v + (size_t)b*SS*HH*EE + h*EE + e;

    float crow[4] = {0.f, 0.f, 0.f, 0.f};

    #pragma unroll
    for (int jc = 0; jc < 4; ++jc) {
        float vloc[16];
        #pragma unroll
        for (int jj = 0; jj < 16; ++jj) vloc[jj] = 0.f;

        #pragma unroll
        for (int m = 0; m < 4; ++m) {
            int i = q*16 + g*4 + m;
            const float* p = vb + (size_t)(i*SDIM + jc*16)*HH*EE;
            #pragma unroll
            for (int jj = 0; jj < 16; ++jj) {
                float val = __ldcs(p + (size_t)jj*HH*EE);
                crow[m] += val;
                vloc[jj] += val;
            }
        }
        #pragma unroll
        for (int jj = 0; jj < 16; ++jj)
            atomicAdd(&sv[(jc*16 + jj)*EE + e], vloc[jj]);
    }

    // Row sums: complete within this block (coalesced over e).
    #pragma unroll
    for (int m = 0; m < 4; ++m) {
        int i = q*16 + g*4 + m;
        g_us[((size_t)bh*SDIM + i)*EE + e] = crow[m];
    }

    __syncthreads();
    float* dst = g_vs4 + ((size_t)q*BB*HH + bh)*SDIM*EE;
    for (int idx = t; idx < SDIM*EE; idx += 256) dst[idx] = sv[idx];
}

// ---------------------------------------------------------------------------
// Kernel 2: 64-tap circular convolutions (the rfft/irfft pair, done directly).
// Merges the 4 partial column-sum slices while loading to smem.
// RxV[k] = sum_j v_s[j] * w[h, (k - j + 64) mod 127]   (same for RxU).
// Writes [b][k][h][e] so k_out streams contiguous 4KB rows.
// ---------------------------------------------------------------------------
__global__ __launch_bounds__(256) void k_conv(const float* __restrict__ w) {
    int bh = blockIdx.x;
    int b = bh >> 4, h = bh & 15;
    int t = threadIdx.x;

    __shared__ float vs_s[SDIM*EE];
    __shared__ float us_s[SDIM*EE];
    __shared__ float w_s[NW];

    const size_t base = (size_t)bh*SDIM*EE;
    const size_t slice = (size_t)BB*HH*SDIM*EE;
    for (int idx = t; idx < SDIM*EE; idx += 256) {
        vs_s[idx] = g_vs4[base + idx] + g_vs4[slice + base + idx]
                  + g_vs4[2*slice + base + idx] + g_vs4[3*slice + base + idx];
        us_s[idx] = g_us[base + idx];
    }
    if (t < NW) w_s[t] = w[h*NW + t];
    __syncthreads();

    int e = t & 63, g = t >> 6;
    for (int k = g; k < SDIM; k += 4) {
        float rv = 0.f, ru = 0.f;
        #pragma unroll
        for (int j = 0; j < SDIM; ++j) {
            int idx = k + 64 - j;            // range [1,127]
            if (idx > 126) idx -= 127;       // 127 -> 0
            float wk = w_s[idx];
            rv += vs_s[j*EE + e] * wk;
            ru += us_s[j*EE + e] * wk;
        }
        size_t o = ((size_t)(b*SDIM + k)*HH + h)*EE + e;
        g_rv[o] = rv;
        g_ru[o] = ru;
    }
}

// ---------------------------------------------------------------------------
// Kernel 3: pbv[b, i*64+j, h, e] = RxV[...,j] + RxU[...,i].
// One block per (b,i); RxU row in registers; RxV rows stay L2-resident
// (__ldg), output written with streaming stores (__stcs) so the 256MB write
// does not evict g_rv from L2.
// ---------------------------------------------------------------------------
__global__ __launch_bounds__(256) void k_out(float* __restrict__ out) {
    int bi = blockIdx.x;            // b*64 + i
    int b = bi >> 6, i = bi & 63;
    int t = threadIdx.x;

    const float4* rowu = reinterpret_cast<const float4*>(g_ru + (size_t)bi*HH*EE);
    float4 uu = __ldg(rowu + t);

    const float4* rvb = reinterpret_cast<const float4*>(g_rv + (size_t)b*SDIM*HH*EE);
    float4* ob = reinterpret_cast<float4*>(out + ((size_t)b*SS + (size_t)i*SDIM)*HH*EE);

    #pragma unroll 8
    for (int j = 0; j < SDIM; ++j) {
        float4 vv = __ldg(rvb + j*(HH*EE/4) + t);
        float4 o;
        o.x = vv.x + uu.x; o.y = vv.y + uu.y;
        o.z = vv.z + uu.z; o.w = vv.w + uu.w;
        __stcs(ob + j*(HH*EE/4) + t, o);
    }
}

// ---------------------------------------------------------------------------
// Kernel 4: z_pb output (65536 floats). zc[h][k] = 64 * conv(o_, w[h])[k],
// out2[(i*64+j)*16 + h] = zc[h][j] + zc[h][i]. One block per i.
// ---------------------------------------------------------------------------
__global__ __launch_bounds__(1024) void k_z(const float* __restrict__ w,
                                            const float* __restrict__ o_,
                                            float* __restrict__ out2) {
    int i = blockIdx.x;     // 0..63
    int t = threadIdx.x;    // 0..1023

    __shared__ float w_s[HH*NW];
    __shared__ float o_s[SDIM];
    __shared__ float zc_s[HH*SDIM];

    for (int idx = t; idx < HH*NW; idx += 1024) w_s[idx] = w[idx];
    if (t < SDIM) o_s[t] = o_[t];
    __syncthreads();

    {
        int h = t >> 6, k = t & 63;
        float acc = 0.f;
        #pragma unroll
        for (int j = 0; j < SDIM; ++j) {
            int idx = k + 64 - j;
            if (idx > 126) idx -= 127;
            acc += o_s[j] * w_s[h*NW + idx];
        }
        zc_s[h*SDIM + k] = acc * 64.f;
    }
    __syncthreads();

    int j = t >> 4, h = t & 15;
    out2[(size_t)i*1024 + t] = zc_s[h*SDIM + j] + zc_s[h*SDIM + i];
}

extern "C" void kernel_launch(void* const* d_in, const int* in_sizes, int n_in,
                              void* d_out, int out_size) {
    const float* v  = (const float*)d_in[0];
    const float* w  = (const float*)d_in[1];
    const float* o_ = (const float*)d_in[2];
    float* out = (float*)d_out;

    k_reduce<<<BB*HH*4, 256>>>(v);
    k_conv  <<<BB*HH, 256>>>(w);
    k_out   <<<BB*SDIM, 256>>>(out);
    k_z     <<<SDIM, 1024>>>(w, o_, out + (size_t)BB*SS*HH*EE);
}

// round 3
// speedup vs baseline: 1.6904x; 1.0176x over previous
#include <cuda_runtime.h>

#define BB 16
#define SS 4096
#define HH 16
#define EE 64
#define SDIM 64
#define NW 127

// Scratch (device globals — no allocation allowed in kernel_launch)
__device__ float g_vs4[4*BB*HH*SDIM*EE]; // [q][b][h][j][e] partial column sums
__device__ float g_us[BB*HH*SDIM*EE];    // [b][h][i][e]    row sums (complete)
__device__ float g_rv[BB*SDIM*HH*EE];    // [b][k][h][e]    RxV
__device__ float g_ru[BB*SDIM*HH*EE];    // [b][k][h][e]    RxU
__device__ float g_zc[HH*SDIM];          // [h][k]          z conv (x64)

// ---------------------------------------------------------------------------
// Kernel 1: row/column sums of v viewed as (b, i, j, h, e), s = i*64+j.
// Grid = 1024: 4 blocks per (b,h), each covering 16 i-rows (q = quarter).
// ---------------------------------------------------------------------------
__global__ __launch_bounds__(256) void k_reduce(const float* __restrict__ v) {
    int bid = blockIdx.x;
    int bh = bid >> 2, q = bid & 3;
    int b = bh >> 4, h = bh & 15;
    int t = threadIdx.x;
    int e = t & 63, g = t >> 6;

    __shared__ float sv[SDIM*EE];
    for (int idx = t; idx < SDIM*EE; idx += 256) sv[idx] = 0.f;
    __syncthreads();

    const float* vb = v + (size_t)b*SS*HH*EE + h*EE + e;

    float crow[4] = {0.f, 0.f, 0.f, 0.f};

    #pragma unroll
    for (int jc = 0; jc < 4; ++jc) {
        float vloc[16];
        #pragma unroll
        for (int jj = 0; jj < 16; ++jj) vloc[jj] = 0.f;

        #pragma unroll
        for (int m = 0; m < 4; ++m) {
            int i = q*16 + g*4 + m;
            const float* p = vb + (size_t)(i*SDIM + jc*16)*HH*EE;
            #pragma unroll
            for (int jj = 0; jj < 16; ++jj) {
                float val = __ldcs(p + (size_t)jj*HH*EE);
                crow[m] += val;
                vloc[jj] += val;
            }
        }
        #pragma unroll
        for (int jj = 0; jj < 16; ++jj)
            atomicAdd(&sv[(jc*16 + jj)*EE + e], vloc[jj]);
    }

    #pragma unroll
    for (int m = 0; m < 4; ++m) {
        int i = q*16 + g*4 + m;
        g_us[((size_t)bh*SDIM + i)*EE + e] = crow[m];
    }

    __syncthreads();
    float* dst = g_vs4 + ((size_t)q*BB*HH + bh)*SDIM*EE;
    for (int idx = t; idx < SDIM*EE; idx += 256) dst[idx] = sv[idx];
}

// ---------------------------------------------------------------------------
// Kernel 2: 64-tap circular convolutions. Merges 4 partial column-sum slices.
// The 16 blocks with b==0 additionally compute zc[h][k] (once, not 64x).
// ---------------------------------------------------------------------------
__global__ __launch_bounds__(256) void k_conv(const float* __restrict__ w,
                                              const float* __restrict__ o_) {
    int bh = blockIdx.x;
    int b = bh >> 4, h = bh & 15;
    int t = threadIdx.x;

    __shared__ float vs_s[SDIM*EE];
    __shared__ float us_s[SDIM*EE];
    __shared__ float w_s[NW];
    __shared__ float o_s[SDIM];

    const size_t base = (size_t)bh*SDIM*EE;
    const size_t slice = (size_t)BB*HH*SDIM*EE;
    for (int idx = t; idx < SDIM*EE; idx += 256) {
        vs_s[idx] = g_vs4[base + idx] + g_vs4[slice + base + idx]
                  + g_vs4[2*slice + base + idx] + g_vs4[3*slice + base + idx];
        us_s[idx] = g_us[base + idx];
    }
    if (t < NW) w_s[t] = w[h*NW + t];
    if (t >= 128 && t < 128 + SDIM) o_s[t - 128] = o_[t - 128];
    __syncthreads();

    // z conv: only once per h (b==0 blocks), threads 0..63
    if (b == 0 && t < SDIM) {
        float acc = 0.f;
        #pragma unroll
        for (int j = 0; j < SDIM; ++j) {
            int idx = t + 64 - j;
            if (idx > 126) idx -= 127;
            acc += o_s[j] * w_s[idx];
        }
        g_zc[h*SDIM + t] = acc * 64.f;
    }

    int e = t & 63, g = t >> 6;
    for (int k = g; k < SDIM; k += 4) {
        float rv = 0.f, ru = 0.f;
        #pragma unroll
        for (int j = 0; j < SDIM; ++j) {
            int idx = k + 64 - j;            // range [1,127]
            if (idx > 126) idx -= 127;       // 127 -> 0
            float wk = w_s[idx];
            rv += vs_s[j*EE + e] * wk;
            ru += us_s[j*EE + e] * wk;
        }
        size_t o = ((size_t)(b*SDIM + k)*HH + h)*EE + e;
        g_rv[o] = rv;
        g_ru[o] = ru;
    }
}

// ---------------------------------------------------------------------------
// Kernel 3: pbv[b, i*64+j, h, e] = RxV[...,j] + RxU[...,i].
// Blocks 0..255: tile of 8 i-rows x 32 j per block. RxU rows (8) live in
// registers; each RxV row loaded once from L2 serves 8 output rows -> L2
// read traffic 36MB instead of 256MB. Streaming stores for the 256MB write.
// Blocks 256..271: write the z_pb output from g_zc (pure broadcast-add).
// ---------------------------------------------------------------------------
__global__ __launch_bounds__(256) void k_out(float* __restrict__ out) {
    int blk = blockIdx.x;
    int t = threadIdx.x;

    if (blk < 256) {
        int b = blk >> 4;
        int itile = (blk >> 1) & 7;     // 0..7  -> i = itile*8 .. +7
        int jhalf = blk & 1;            // 0..1  -> j = jhalf*32 .. +31

        const float4* rub = reinterpret_cast<const float4*>(g_ru + (size_t)b*SDIM*HH*EE);
        const float4* rvb = reinterpret_cast<const float4*>(g_rv + (size_t)b*SDIM*HH*EE);
        float4* ob = reinterpret_cast<float4*>(out + (size_t)b*SS*HH*EE);

        float4 uu[8];
        #pragma unroll
        for (int m = 0; m < 8; ++m)
            uu[m] = __ldg(rub + (itile*8 + m)*(HH*EE/4) + t);

        #pragma unroll 4
        for (int jj = 0; jj < 32; ++jj) {
            int j = jhalf*32 + jj;
            float4 vv = __ldg(rvb + j*(HH*EE/4) + t);
            #pragma unroll
            for (int m = 0; m < 8; ++m) {
                int i = itile*8 + m;
                float4 o;
                o.x = vv.x + uu[m].x; o.y = vv.y + uu[m].y;
                o.z = vv.z + uu[m].z; o.w = vv.w + uu[m].w;
                __stcs(ob + ((size_t)i*SDIM + j)*(HH*EE/4) + t, o);
            }
        }
    } else {
        // z_pb writer: 16 blocks, each covers 4 i-rows of out2.
        int zi = blk - 256;             // 0..15 -> i = zi*4 .. +3
        __shared__ float zc[HH*SDIM];
        for (int idx = t; idx < HH*SDIM; idx += 256) zc[idx] = g_zc[idx];
        __syncthreads();

        float* o2 = out + (size_t)BB*SS*HH*EE;
        #pragma unroll
        for (int r = 0; r < 4; ++r) {
            int i = zi*4 + r;
            #pragma unroll
            for (int it = 0; it < 4; ++it) {
                int idx = it*256 + t;       // 0..1023
                int j = idx >> 4, h = idx & 15;
                o2[(size_t)i*1024 + idx] = zc[h*SDIM + j] + zc[h*SDIM + i];
            }
        }
    }
}

extern "C" void kernel_launch(void* const* d_in, const int* in_sizes, int n_in,
                              void* d_out, int out_size) {
    const float* v  = (const float*)d_in[0];
    const float* w  = (const float*)d_in[1];
    const float* o_ = (const float*)d_in[2];
    float* out = (float*)d_out;

    k_reduce<<<BB*HH*4, 256>>>(v);
    k_conv  <<<BB*HH, 256>>>(w, o_);
    k_out   <<<256 + 16, 256>>>(out);
}

// round 4
// speedup vs baseline: 2.0009x; 1.1837x over previous
#include <cuda_runtime.h>

#define BB 16
#define SS 4096
#define HH 16
#define EE 64
#define SDIM 64
#define NW 127

// Scratch (device globals — no allocation allowed in kernel_launch)
__device__ float g_vs2[2*BB*HH*SDIM*EE]; // [half][b][h][j][e] partial column sums
__device__ float g_us[BB*HH*SDIM*EE];    // [b][h][i][e]       row sums (complete)
__device__ float g_rv[BB*SDIM*HH*EE];    // [b][k][h][e]       RxV
__device__ float g_ru[BB*SDIM*HH*EE];    // [b][k][h][e]       RxU
__device__ float g_zc[HH*SDIM];          // [h][k]             z conv (x64)

// ---------------------------------------------------------------------------
// Kernel 1: row/column sums of v viewed as (b, i, j, h, e), s = i*64+j.
// Grid = 512: (bh, half). Block covers 32 i-rows. Thread: e4 = t&15 (float4
// over e), g = t>>4 (16 groups), each group owns i = half*32 + g*2 + {0,1}.
// All loads are LDG.128 (__ldcs, read-once). j runs in chunks of 8:
// vloc4[8] accumulates the 2 i's; cross-group column reduction is a staged
// smem tree (no atomics): 16 groups write partials, 128 threads sum and
// store straight to a 2-slice global partial merged by k_conv. Row sums
// accumulate in registers (thread sees all 64 j) -> coalesced float4 store.
// ---------------------------------------------------------------------------
__global__ __launch_bounds__(256) void k_reduce(const float* __restrict__ v) {
    int bid = blockIdx.x;
    int bh = bid >> 1, half = bid & 1;
    int b = bh >> 4, h = bh & 15;
    int t = threadIdx.x;
    int e4 = t & 15, g = t >> 4;

    __shared__ float4 stage[16*8*16];   // [g][jj][e4]  32KB

    // float4 view of v: row (s) stride = 256 float4
    const float4* v4 = reinterpret_cast<const float4*>(v)
                     + (size_t)b*SS*(HH*EE/4) + h*(EE/4) + e4;

    int i0 = half*32 + g*2;
    float4 crow0 = make_float4(0.f,0.f,0.f,0.f);
    float4 crow1 = make_float4(0.f,0.f,0.f,0.f);

    float* vs_dst = g_vs2 + ((size_t)(half*BB*HH + bh)*SDIM)*EE;

    #pragma unroll 1
    for (int jc = 0; jc < 8; ++jc) {
        float4 vloc[8];
        const float4* p0 = v4 + (size_t)(i0*SDIM + jc*8)*(HH*EE/4);
        const float4* p1 = p0 + (size_t)SDIM*(HH*EE/4);
        #pragma unroll
        for (int jj = 0; jj < 8; ++jj) {
            float4 a = __ldcs(p0 + (size_t)jj*(HH*EE/4));
            float4 c = __ldcs(p1 + (size_t)jj*(HH*EE/4));
            crow0.x += a.x; crow0.y += a.y; crow0.z += a.z; crow0.w += a.w;
            crow1.x += c.x; crow1.y += c.y; crow1.z += c.z; crow1.w += c.w;
            vloc[jj] = make_float4(a.x + c.x, a.y + c.y, a.z + c.z, a.w + c.w);
        }
        #pragma unroll
        for (int jj = 0; jj < 8; ++jj)
            stage[(g*8 + jj)*16 + e4] = vloc[jj];
        __syncthreads();

        if (t < 128) {
            int jj = t >> 4, ee = t & 15;
            float4 s = stage[jj*16 + ee];
            #pragma unroll
            for (int gg = 1; gg < 16; ++gg) {
                float4 x = stage[(gg*8 + jj)*16 + ee];
                s.x += x.x; s.y += x.y; s.z += x.z; s.w += x.w;
            }
            reinterpret_cast<float4*>(vs_dst + (jc*8 + jj)*EE)[ee] = s;
        }
        __syncthreads();
    }

    // Row sums (complete: thread covered all 64 j for its 2 i's).
    float4* us4 = reinterpret_cast<float4*>(g_us + (size_t)bh*SDIM*EE);
    us4[(i0    )*(EE/4) + e4] = crow0;
    us4[(i0 + 1)*(EE/4) + e4] = crow1;
}

// ---------------------------------------------------------------------------
// Kernel 2: 64-tap circular convolutions. Merges 2 partial column-sum slices.
// The 16 blocks with b==0 additionally compute zc[h][k] (once).
// RxV[k] = sum_j v_s[j] * w[h, (k - j + 64) mod 127]   (same for RxU).
// Writes [b][k][h][e] so k_out streams contiguous 4KB rows.
// ---------------------------------------------------------------------------
__global__ __launch_bounds__(256) void k_conv(const float* __restrict__ w,
                                              const float* __restrict__ o_) {
    int bh = blockIdx.x;
    int b = bh >> 4, h = bh & 15;
    int t = threadIdx.x;

    __shared__ float vs_s[SDIM*EE];
    __shared__ float us_s[SDIM*EE];
    __shared__ float w_s[NW];
    __shared__ float o_s[SDIM];

    const size_t base = (size_t)bh*SDIM*EE;
    const size_t slice = (size_t)BB*HH*SDIM*EE;
    for (int idx = t; idx < SDIM*EE; idx += 256) {
        vs_s[idx] = g_vs2[base + idx] + g_vs2[slice + base + idx];
        us_s[idx] = g_us[base + idx];
    }
    if (t < NW) w_s[t] = w[h*NW + t];
    if (t >= 128 && t < 128 + SDIM) o_s[t - 128] = o_[t - 128];
    __syncthreads();

    // z conv: only once per h (b==0 blocks), threads 0..63
    if (b == 0 && t < SDIM) {
        float acc = 0.f;
        #pragma unroll
        for (int j = 0; j < SDIM; ++j) {
            int idx = t + 64 - j;
            if (idx > 126) idx -= 127;
            acc += o_s[j] * w_s[idx];
        }
        g_zc[h*SDIM + t] = acc * 64.f;
    }

    int e = t & 63, g = t >> 6;
    for (int k = g; k < SDIM; k += 4) {
        float rv = 0.f, ru = 0.f;
        #pragma unroll
        for (int j = 0; j < SDIM; ++j) {
            int idx = k + 64 - j;            // range [1,127]
            if (idx > 126) idx -= 127;       // 127 -> 0
            float wk = w_s[idx];
            rv += vs_s[j*EE + e] * wk;
            ru += us_s[j*EE + e] * wk;
        }
        size_t o = ((size_t)(b*SDIM + k)*HH + h)*EE + e;
        g_rv[o] = rv;
        g_ru[o] = ru;
    }
}

// ---------------------------------------------------------------------------
// Kernel 3: pbv[b, i*64+j, h, e] = RxV[...,j] + RxU[...,i].
// Blocks 0..1023: tile 8 i-rows x 8 j per block (16b x 8it x 8jt), 6.9
// blocks/SM (balanced). RxU rows in registers; each RxV row from L2 serves
// 8 output rows. Streaming stores for the 256MB write.
// Blocks 1024..1039: write the z_pb output from g_zc.
// ---------------------------------------------------------------------------
__global__ __launch_bounds__(256) void k_out(float* __restrict__ out) {
    int blk = blockIdx.x;
    int t = threadIdx.x;

    if (blk < 1024) {
        int b = blk >> 6;
        int itile = (blk >> 3) & 7;     // i = itile*8 .. +7
        int jt = blk & 7;               // j = jt*8 .. +7

        const float4* rub = reinterpret_cast<const float4*>(g_ru + (size_t)b*SDIM*HH*EE);
        const float4* rvb = reinterpret_cast<const float4*>(g_rv + (size_t)b*SDIM*HH*EE);
        float4* ob = reinterpret_cast<float4*>(out + (size_t)b*SS*HH*EE);

        float4 uu[8];
        #pragma unroll
        for (int m = 0; m < 8; ++m)
            uu[m] = __ldg(rub + (itile*8 + m)*(HH*EE/4) + t);

        #pragma unroll
        for (int jj = 0; jj < 8; ++jj) {
            int j = jt*8 + jj;
            float4 vv = __ldg(rvb + j*(HH*EE/4) + t);
            #pragma unroll
            for (int m = 0; m < 8; ++m) {
                int i = itile*8 + m;
                float4 o;
                o.x = vv.x + uu[m].x; o.y = vv.y + uu[m].y;
                o.z = vv.z + uu[m].z; o.w = vv.w + uu[m].w;
                __stcs(ob + ((size_t)i*SDIM + j)*(HH*EE/4) + t, o);
            }
        }
    } else {
        // z_pb writer: 16 blocks, each covers 4 i-rows of out2.
        int zi = blk - 1024;            // 0..15 -> i = zi*4 .. +3
        __shared__ float zc[HH*SDIM];
        for (int idx = t; idx < HH*SDIM; idx += 256) zc[idx] = g_zc[idx];
        __syncthreads();

        float* o2 = out + (size_t)BB*SS*HH*EE;
        #pragma unroll
        for (int r = 0; r < 4; ++r) {
            int i = zi*4 + r;
            #pragma unroll
            for (int it = 0; it < 4; ++it) {
                int idx = it*256 + t;       // 0..1023
                int j = idx >> 4, h = idx & 15;
                o2[(size_t)i*1024 + idx] = zc[h*SDIM + j] + zc[h*SDIM + i];
            }
        }
    }
}

extern "C" void kernel_launch(void* const* d_in, const int* in_sizes, int n_in,
                              void* d_out, int out_size) {
    const float* v  = (const float*)d_in[0];
    const float* w  = (const float*)d_in[1];
    const float* o_ = (const float*)d_in[2];
    float* out = (float*)d_out;

    k_reduce<<<BB*HH*2, 256>>>(v);
    k_conv  <<<BB*HH, 256>>>(w, o_);
    k_out   <<<1024 + 16, 256>>>(out);
}

// round 5
// speedup vs baseline: 2.0727x; 1.0359x over previous
#include <cuda_runtime.h>

#define BB 16
#define SS 4096
#define HH 16
#define EE 64
#define SDIM 64
#define NW 127

// Scratch (device globals — no allocation allowed in kernel_launch)
__device__ float g_vs2[2*BB*HH*SDIM*EE]; // [half][b][h][j][e] partial column sums
__device__ float g_us[BB*HH*SDIM*EE];    // [b][h][i][e]       row sums (complete)
__device__ float g_rv[BB*SDIM*HH*EE];    // [b][k][h][e]       RxV
__device__ float g_ru[BB*SDIM*HH*EE];    // [b][k][h][e]       RxU
__device__ float g_zc[HH*SDIM];          // [h][k]             z conv (x64)

// ---------------------------------------------------------------------------
// Kernel 1: row/column sums of v viewed as (b, i, j, h, e), s = i*64+j.
// Grid = 512: (bh, half). Block covers 32 i. Warp w owns i = half*32+w*4+sub*2
// +{0,1} (sub = half-warp). Inner: 16 LDG.128/thread per 8-j chunk; half-warp
// pairs combine column partials via shfl_down(16); lanes<16 stage 8-warp
// partials to a DOUBLE-BUFFERED 16KB stage. ONE barrier per chunk: the half
// of the block not reducing this chunk immediately issues the next chunk's
// loads, keeping DRAM busy through the reduction. Row sums stay in registers.
// ---------------------------------------------------------------------------
__global__ __launch_bounds__(256) void k_reduce(const float* __restrict__ v) {
    int bid = blockIdx.x;
    int bh = bid >> 1, half = bid & 1;
    int b = bh >> 4, h = bh & 15;
    int t = threadIdx.x;
    int e4 = t & 15, sub = (t >> 4) & 1, w = t >> 5;

    __shared__ float4 stage[2][8*8*16];   // [buf][w*8+jj][e4]  2 x 16KB

    const float4* v4 = reinterpret_cast<const float4*>(v)
                     + (size_t)b*SS*(HH*EE/4) + h*(EE/4) + e4;

    int i0 = half*32 + w*4 + sub*2;
    float4 crow0 = make_float4(0.f,0.f,0.f,0.f);
    float4 crow1 = make_float4(0.f,0.f,0.f,0.f);

    float* vs_dst = g_vs2 + (size_t)(half*BB*HH + bh)*SDIM*EE;

    #pragma unroll 1
    for (int jc = 0; jc < 8; ++jc) {
        float4 vloc[8];
        const float4* p0 = v4 + (size_t)(i0*SDIM + jc*8)*(HH*EE/4);
        const float4* p1 = p0 + (size_t)SDIM*(HH*EE/4);
        #pragma unroll
        for (int jj = 0; jj < 8; ++jj) {
            float4 a = __ldcs(p0 + (size_t)jj*(HH*EE/4));
            float4 c = __ldcs(p1 + (size_t)jj*(HH*EE/4));
            crow0.x += a.x; crow0.y += a.y; crow0.z += a.z; crow0.w += a.w;
            crow1.x += c.x; crow1.y += c.y; crow1.z += c.z; crow1.w += c.w;
            vloc[jj] = make_float4(a.x + c.x, a.y + c.y, a.z + c.z, a.w + c.w);
        }
        // combine the two half-warps (sub 0/1 hold different i-pairs, same j/e)
        #pragma unroll
        for (int jj = 0; jj < 8; ++jj) {
            vloc[jj].x += __shfl_down_sync(0xffffffffu, vloc[jj].x, 16);
            vloc[jj].y += __shfl_down_sync(0xffffffffu, vloc[jj].y, 16);
            vloc[jj].z += __shfl_down_sync(0xffffffffu, vloc[jj].z, 16);
            vloc[jj].w += __shfl_down_sync(0xffffffffu, vloc[jj].w, 16);
        }
        if (sub == 0) {
            #pragma unroll
            for (int jj = 0; jj < 8; ++jj)
                stage[jc & 1][(w*8 + jj)*16 + e4] = vloc[jj];
        }
        __syncthreads();

        // Alternate which half of the block reduces, so the other half moves
        // straight on to the next chunk's global loads.
        bool lower = (t < 128);
        if (lower == ((jc & 1) == 0)) {
            int tt = t & 127;
            int jj = tt >> 4, ee = tt & 15;
            float4 s = stage[jc & 1][jj*16 + ee];
            #pragma unroll
            for (int ww = 1; ww < 8; ++ww) {
                float4 x = stage[jc & 1][(ww*8 + jj)*16 + ee];
                s.x += x.x; s.y += x.y; s.z += x.z; s.w += x.w;
            }
            reinterpret_cast<float4*>(vs_dst + (jc*8 + jj)*EE)[ee] = s;
        }
    }

    // Row sums (complete: thread covered all 64 j for its 2 i's).
    float4* us4 = reinterpret_cast<float4*>(g_us + (size_t)bh*SDIM*EE);
    us4[(i0    )*(EE/4) + e4] = crow0;
    us4[(i0 + 1)*(EE/4) + e4] = crow1;
}

// ---------------------------------------------------------------------------
// Kernel 2: 64-tap circular convolutions. Grid 512: 2 blocks per (b,h), each
// covering half the k range (FMA-bound -> split). Merges the 2 partial
// column-sum slices with float4 loads. b==0,kh==0 blocks also compute zc.
// ---------------------------------------------------------------------------
__global__ __launch_bounds__(256) void k_conv(const float* __restrict__ w,
                                              const float* __restrict__ o_) {
    int blk = blockIdx.x;
    int bh = blk >> 1, kh = blk & 1;
    int b = bh >> 4, h = bh & 15;
    int t = threadIdx.x;

    __shared__ float vs_s[SDIM*EE];
    __shared__ float us_s[SDIM*EE];
    __shared__ float w_s[NW];
    __shared__ float o_s[SDIM];

    const size_t base = (size_t)bh*SDIM*EE;
    const size_t slice = (size_t)BB*HH*SDIM*EE;
    {
        const float4* pa = reinterpret_cast<const float4*>(g_vs2 + base);
        const float4* pb = reinterpret_cast<const float4*>(g_vs2 + slice + base);
        const float4* pu = reinterpret_cast<const float4*>(g_us + base);
        float4* vsv = reinterpret_cast<float4*>(vs_s);
        float4* usv = reinterpret_cast<float4*>(us_s);
        #pragma unroll
        for (int r = 0; r < 4; ++r) {
            int idx = r*256 + t;
            float4 x = __ldg(pa + idx), y = __ldg(pb + idx);
            vsv[idx] = make_float4(x.x+y.x, x.y+y.y, x.z+y.z, x.w+y.w);
            usv[idx] = __ldg(pu + idx);
        }
    }
    if (t < NW) w_s[t] = w[h*NW + t];
    if (t >= 128 && t < 128 + SDIM) o_s[t - 128] = o_[t - 128];
    __syncthreads();

    if (b == 0 && kh == 0 && t < SDIM) {
        float acc = 0.f;
        #pragma unroll
        for (int j = 0; j < SDIM; ++j) {
            int idx = t + 64 - j;
            if (idx > 126) idx -= 127;
            acc += o_s[j] * w_s[idx];
        }
        g_zc[h*SDIM + t] = acc * 64.f;
    }

    int e = t & 63, g = t >> 6;
    #pragma unroll 1
    for (int k = kh*32 + g; k < kh*32 + 32; k += 4) {
        float rv = 0.f, ru = 0.f;
        #pragma unroll
        for (int j = 0; j < SDIM; ++j) {
            int idx = k + 64 - j;            // range [1,127]
            if (idx > 126) idx -= 127;       // 127 -> 0
            float wk = w_s[idx];
            rv += vs_s[j*EE + e] * wk;
            ru += us_s[j*EE + e] * wk;
        }
        size_t o = ((size_t)(b*SDIM + k)*HH + h)*EE + e;
        g_rv[o] = rv;
        g_ru[o] = ru;
    }
}

// ---------------------------------------------------------------------------
// Kernel 3: pbv[b, i*64+j, h, e] = RxV[...,j] + RxU[...,i].
// Blocks 0..1023: tile 8 i x 8 j; RxU rows in registers, each RxV row from
// L2 serves 8 output rows; streaming stores for the 256MB write.
// Blocks 1024..1039: z_pb output from g_zc.
// ---------------------------------------------------------------------------
__global__ __launch_bounds__(256) void k_out(float* __restrict__ out) {
    int blk = blockIdx.x;
    int t = threadIdx.x;

    if (blk < 1024) {
        int b = blk >> 6;
        int itile = (blk >> 3) & 7;
        int jt = blk & 7;

        const float4* rub = reinterpret_cast<const float4*>(g_ru + (size_t)b*SDIM*HH*EE);
        const float4* rvb = reinterpret_cast<const float4*>(g_rv + (size_t)b*SDIM*HH*EE);
        float4* ob = reinterpret_cast<float4*>(out + (size_t)b*SS*HH*EE);

        float4 uu[8];
        #pragma unroll
        for (int m = 0; m < 8; ++m)
            uu[m] = __ldg(rub + (itile*8 + m)*(HH*EE/4) + t);

        #pragma unroll
        for (int jj = 0; jj < 8; ++jj) {
            int j = jt*8 + jj;
            float4 vv = __ldg(rvb + j*(HH*EE/4) + t);
            #pragma unroll
            for (int m = 0; m < 8; ++m) {
                int i = itile*8 + m;
                float4 o;
                o.x = vv.x + uu[m].x; o.y = vv.y + uu[m].y;
                o.z = vv.z + uu[m].z; o.w = vv.w + uu[m].w;
                __stcs(ob + ((size_t)i*SDIM + j)*(HH*EE/4) + t, o);
            }
        }
    } else {
        int zi = blk - 1024;
        __shared__ float zc[HH*SDIM];
        for (int idx = t; idx < HH*SDIM; idx += 256) zc[idx] = g_zc[idx];
        __syncthreads();

        float* o2 = out + (size_t)BB*SS*HH*EE;
        #pragma unroll
        for (int r = 0; r < 4; ++r) {
            int i = zi*4 + r;
            #pragma unroll
            for (int it = 0; it < 4; ++it) {
                int idx = it*256 + t;
                int j = idx >> 4, h = idx & 15;
                o2[(size_t)i*1024 + idx] = zc[h*SDIM + j] + zc[h*SDIM + i];
            }
        }
    }
}

extern "C" void kernel_launch(void* const* d_in, const int* in_sizes, int n_in,
                              void* d_out, int out_size) {
    const float* v  = (const float*)d_in[0];
    const float* w  = (const float*)d_in[1];
    const float* o_ = (const float*)d_in[2];
    float* out = (float*)d_out;

    k_reduce<<<BB*HH*2, 256>>>(v);
    k_conv  <<<BB*HH*2, 256>>>(w, o_);
    k_out   <<<1024 + 16, 256>>>(out);
}